// round 13
// baseline (speedup 1.0000x reference)
#include <cuda_runtime.h>
#include <cuda_bf16.h>
#include <math.h>
#include <stdint.h>

#define TT 2048
#define BB 4
#define CCD 1024
#define QD 256
#define KVD 32
#define NPROJ 320
#define NROWS (BB*TT)       // 8192
#define VOCAB 50257

// ---------------- scratch (static device globals; no allocations) ----------------
__device__ __align__(16) float d_proj[NROWS * NPROJ];
__device__ __align__(16) float d_kraw[NROWS * QD];
__device__ __align__(16) float d_vraw[NROWS * CCD];
__device__ __align__(16) __nv_bfloat16 d_xh[NROWS * CCD];
__device__ __align__(16) __nv_bfloat16 d_xl[NROWS * CCD];
__device__ __align__(16) __nv_bfloat16 d_wh[NPROJ * CCD];
__device__ __align__(16) __nv_bfloat16 d_wl[NPROJ * CCD];
__device__ __align__(16) __nv_bfloat16 d_qh[NROWS * QD];
__device__ __align__(16) __nv_bfloat16 d_ql[NROWS * QD];
__device__ __align__(16) __nv_bfloat16 d_kh[NROWS * QD];
__device__ __align__(16) __nv_bfloat16 d_kl[NROWS * QD];
__device__ __align__(16) __nv_bfloat16 d_vth[(size_t)NROWS * CCD];  // [b][c][t]
__device__ __align__(16) __nv_bfloat16 d_vtl[(size_t)NROWS * CCD];
__device__ __align__(16) __nv_bfloat16 d_ph[(size_t)BB * TT * TT];  // P hi, [b][t][s]
__device__ __align__(16) __nv_bfloat16 d_pl[(size_t)BB * TT * TT];  // P lo
__device__ float d_psum[(size_t)NROWS * 64];
__device__ float d_rowsum[NROWS];
__device__ float d_vmean[NROWS];
__device__ float d_vrstd[NROWS];
__device__ int   d_idx32[NROWS];

// ---------------- warp-mma / async helpers ----------------
__device__ __forceinline__ uint32_t smem_to_u32(const void* p) {
    uint32_t a;
    asm("{ .reg .u64 t; cvta.to.shared.u64 t, %1; cvt.u32.u64 %0, t; }" : "=r"(a) : "l"(p));
    return a;
}
__device__ __forceinline__ void ldsm4(uint32_t r[4], uint32_t a) {
    asm volatile("ldmatrix.sync.aligned.m8n8.x4.shared.b16 {%0,%1,%2,%3}, [%4];"
                 : "=r"(r[0]), "=r"(r[1]), "=r"(r[2]), "=r"(r[3]) : "r"(a));
}
__device__ __forceinline__ void ldsm2(uint32_t r[2], uint32_t a) {
    asm volatile("ldmatrix.sync.aligned.m8n8.x2.shared.b16 {%0,%1}, [%2];"
                 : "=r"(r[0]), "=r"(r[1]) : "r"(a));
}
__device__ __forceinline__ void mma_bf16(float c[4], const uint32_t a[4], const uint32_t b[2]) {
    asm volatile("mma.sync.aligned.m16n8k16.row.col.f32.bf16.bf16.f32 "
                 "{%0,%1,%2,%3}, {%4,%5,%6,%7}, {%8,%9}, {%0,%1,%2,%3};"
                 : "+f"(c[0]), "+f"(c[1]), "+f"(c[2]), "+f"(c[3])
                 : "r"(a[0]), "r"(a[1]), "r"(a[2]), "r"(a[3]), "r"(b[0]), "r"(b[1]));
}
__device__ __forceinline__ uint32_t pack_bf16x2(float lo, float hi) {
    uint32_t r;
    asm("cvt.rn.bf16x2.f32 %0, %1, %2;" : "=r"(r) : "f"(hi), "f"(lo));
    return r;
}
__device__ __forceinline__ void cp_async16(uint32_t sdst, const void* gsrc) {
    asm volatile("cp.async.ca.shared.global [%0], [%1], 16;" :: "r"(sdst), "l"(gsrc) : "memory");
}
#define CP_COMMIT() asm volatile("cp.async.commit_group;" ::: "memory")
#define CP_WAIT3()  asm volatile("cp.async.wait_group 3;" ::: "memory")
#define CP_WAIT2()  asm volatile("cp.async.wait_group 2;" ::: "memory")
#define CP_WAIT0()  asm volatile("cp.async.wait_group 0;" ::: "memory")

// pv/score: 3 stages x 4 arrays x (128 rows x 48B)
#define PV_ARR   6144
#define PV_STAGE 24576
#define PV_SMEM  73728
// proj: 4 stages x (A 128x48 x2 + B 64x48 x2)
#define PJ_AL    6144
#define PJ_BH    12288
#define PJ_BL    15360
#define PJ_STAGE 18432
#define PJ_SMEM  73728

// =====================================================================
// K0: idx normalize (int32/int64 auto-detect)
// =====================================================================
__global__ void idx_cvt_kernel(const void* __restrict__ raw) {
    const long long* p64 = (const long long*)raw;
    const int*       p32 = (const int*)raw;
    bool is64 = true;
    #pragma unroll
    for (int i = 0; i < 16; i++) {
        long long v = p64[i];
        if (v < 0 || v >= (long long)VOCAB) is64 = false;
    }
    int i = blockIdx.x * blockDim.x + threadIdx.x;
    if (i < NROWS) {
        int v = is64 ? (int)p64[i] : p32[i];
        if (v < 0) v = 0;
        if (v >= VOCAB) v = VOCAB - 1;
        d_idx32[i] = v;
    }
}

// =====================================================================
// K0b: splits (dest resolved device-side — ATS pitfall)
// =====================================================================
__global__ void xsplit_kernel(const float* __restrict__ src, int n4) {
    int i = blockIdx.x * 256 + threadIdx.x;
    if (i >= n4) return;
    float4 v = ((const float4*)src)[i];
    float hx = __bfloat162float(__float2bfloat16(v.x));
    float hy = __bfloat162float(__float2bfloat16(v.y));
    float hz = __bfloat162float(__float2bfloat16(v.z));
    float hw = __bfloat162float(__float2bfloat16(v.w));
    ((uint2*)d_xh)[i] = make_uint2(pack_bf16x2(hx, hy), pack_bf16x2(hz, hw));
    ((uint2*)d_xl)[i] = make_uint2(pack_bf16x2(v.x - hx, v.y - hy), pack_bf16x2(v.z - hz, v.w - hw));
}

__global__ void wsplit_kernel(const float* __restrict__ Wqq, const float* __restrict__ Wk,
                              const float* __restrict__ Wv) {
    int i = blockIdx.x * 256 + threadIdx.x;
    if (i >= NPROJ * CCD / 4) return;
    int row = i >> 8;
    int c4  = i & 255;
    const float* src;
    if (row < 256)      src = Wqq + (size_t)row * CCD;
    else if (row < 288) src = Wk  + (size_t)(row - 256) * CCD;
    else                src = Wv  + (size_t)(row - 288) * CCD;
    float4 v = ((const float4*)src)[c4];
    float hx = __bfloat162float(__float2bfloat16(v.x));
    float hy = __bfloat162float(__float2bfloat16(v.y));
    float hz = __bfloat162float(__float2bfloat16(v.z));
    float hw = __bfloat162float(__float2bfloat16(v.w));
    ((uint2*)d_wh)[i] = make_uint2(pack_bf16x2(hx, hy), pack_bf16x2(hz, hw));
    ((uint2*)d_wl)[i] = make_uint2(pack_bf16x2(v.x - hx, v.y - hy), pack_bf16x2(v.z - hz, v.w - hw));
}

// =====================================================================
// K1: projection GEMM via mma.sync, cp.async 4-stage pipeline (k16)
// =====================================================================
__global__ void __launch_bounds__(256, 2) proj_mma_kernel() {
    extern __shared__ char smem[];
    const int nb = blockIdx.x * 64;
    const int mb = blockIdx.y * 128;
    const uint32_t sb = smem_to_u32(smem);
    const int tid  = threadIdx.x;
    const int lane = tid & 31;
    const int wid  = tid >> 5;
    const int wm = wid & 1;
    const int wn = wid >> 1;
    const int g = lane >> 2, q = lane & 3;

    float acc[4][2][4] = {};

    const int lrow = tid >> 1;
    const int lh   = tid & 1;
    const __nv_bfloat16* gah = d_xh + (size_t)(mb + lrow) * CCD + lh * 8;
    const __nv_bfloat16* gal = d_xl + (size_t)(mb + lrow) * CCD + lh * 8;
    const uint32_t sadst = sb + lrow * 48 + lh * 16;
    const bool bload = tid < 128;
    const __nv_bfloat16* gbh = d_wh + (size_t)(nb + (tid >> 1)) * CCD + lh * 8;
    const __nv_bfloat16* gbl = d_wl + (size_t)(nb + (tid >> 1)) * CCD + lh * 8;
    const uint32_t sbdst = sb + (tid >> 1) * 48 + lh * 16;

    const int nc = CCD / 16;            // 64 chunks

    // prologue: stages 0..2
    #pragma unroll
    for (int p = 0; p < 3; p++) {
        const uint32_t st = p * PJ_STAGE;
        const int k = p * 16;
        cp_async16(sadst + st, gah + k);
        cp_async16(sadst + st + PJ_AL, gal + k);
        if (bload) { cp_async16(sbdst + st + PJ_BH, gbh + k); cp_async16(sbdst + st + PJ_BL, gbl + k); }
        CP_COMMIT();
    }

    for (int c = 0; c < nc; c++) {
        const uint32_t st = (c & 3) * PJ_STAGE;
        if (c + 3 < nc) {
            const uint32_t st2 = ((c + 3) & 3) * PJ_STAGE;
            const int k1 = (c + 3) * 16;
            cp_async16(sadst + st2, gah + k1);
            cp_async16(sadst + st2 + PJ_AL, gal + k1);
            if (bload) { cp_async16(sbdst + st2 + PJ_BH, gbh + k1); cp_async16(sbdst + st2 + PJ_BL, gbl + k1); }
            CP_COMMIT();
            CP_WAIT3();
        } else {
            CP_WAIT0();
        }
        __syncthreads();
        {
            uint32_t bh[2][2], bl[2][2];
            const int brw = lane & 7;
            const uint32_t bsel = ((lane >> 3) & 1) * 16;
            #pragma unroll
            for (int ni = 0; ni < 2; ni++) {
                uint32_t boff = (wn * 16 + ni * 8 + brw) * 48 + bsel;
                ldsm2(bh[ni], sb + st + PJ_BH + boff);
                ldsm2(bl[ni], sb + st + PJ_BL + boff);
            }
            const int arw = wm * 64 + (lane & 15);
            const uint32_t asel = (lane >> 4) * 16;
            #pragma unroll
            for (int mi = 0; mi < 4; mi++) {
                uint32_t ah[4], al[4];
                uint32_t aoff = (arw + mi * 16) * 48 + asel;
                ldsm4(ah, sb + st + aoff);
                ldsm4(al, sb + st + PJ_AL + aoff);
                #pragma unroll
                for (int ni = 0; ni < 2; ni++) {
                    mma_bf16(acc[mi][ni], ah, bh[ni]);
                    mma_bf16(acc[mi][ni], ah, bl[ni]);
                    mma_bf16(acc[mi][ni], al, bh[ni]);
                }
            }
        }
        __syncthreads();
    }
    #pragma unroll
    for (int mi = 0; mi < 4; mi++) {
        const int r0 = mb + wm * 64 + mi * 16 + g;
        #pragma unroll
        for (int ni = 0; ni < 2; ni++) {
            const int c = nb + wn * 16 + ni * 8 + q * 2;
            *(float2*)&d_proj[(size_t)r0 * NPROJ + c]       = make_float2(acc[mi][ni][0], acc[mi][ni][1]);
            *(float2*)&d_proj[(size_t)(r0 + 8) * NPROJ + c] = make_float2(acc[mi][ni][2], acc[mi][ni][3]);
        }
    }
}

// =====================================================================
// K2a/K2b: low-rank up-projections (unchanged)
// =====================================================================
__global__ void kup_kernel(const float* __restrict__ Wkup, const float* __restrict__ ktab) {
    __shared__ float Ws[32 * 257];
    __shared__ float kds[32][32];
    const int tid = threadIdx.x;
    const int r0 = blockIdx.x * 32;
    for (int i2 = tid; i2 < QD * KVD; i2 += 256) {
        int o = i2 >> 5, d = i2 & 31;
        Ws[d * 257 + o] = Wkup[i2];
    }
    for (int i2 = tid; i2 < 32 * KVD; i2 += 256) {
        int rr = i2 >> 5, d = i2 & 31;
        kds[rr][d] = d_proj[(size_t)(r0 + rr) * NPROJ + 256 + d];
    }
    __syncthreads();
    float a[32];
    #pragma unroll
    for (int rr = 0; rr < 32; rr++) a[rr] = 0.f;
    #pragma unroll
    for (int d = 0; d < 32; d++) {
        float w = Ws[d * 257 + tid];
        #pragma unroll
        for (int rr = 0; rr < 32; rr++) a[rr] += kds[rr][d] * w;
    }
    #pragma unroll
    for (int rr = 0; rr < 32; rr++) {
        int ii = d_idx32[r0 + rr];
        d_kraw[(size_t)(r0 + rr) * QD + tid] = a[rr] * ktab[(size_t)ii * QD + tid];
    }
}

__global__ void vup_kernel(const float* __restrict__ Wvup, const float* __restrict__ vtab) {
    __shared__ float Wtc[32 * 257];
    __shared__ float vds[16][32];
    const int tid = threadIdx.x;
    const int r0 = blockIdx.x * 16;
    for (int i2 = tid; i2 < 16 * KVD; i2 += 256) {
        int rr = i2 >> 5, d = i2 & 31;
        vds[rr][d] = d_proj[(size_t)(r0 + rr) * NPROJ + 288 + d];
    }
    for (int j = 0; j < 4; j++) {
        __syncthreads();
        for (int i2 = tid; i2 < 256 * KVD; i2 += 256) {
            int cl = i2 >> 5, d = i2 & 31;
            Wtc[d * 257 + cl] = Wvup[(size_t)(j * 256 + cl) * KVD + d];
        }
        __syncthreads();
        const int c = j * 256 + tid;
        float a[16];
        #pragma unroll
        for (int rr = 0; rr < 16; rr++) a[rr] = 0.f;
        #pragma unroll
        for (int d = 0; d < 32; d++) {
            float w = Wtc[d * 257 + tid];
            #pragma unroll
            for (int rr = 0; rr < 16; rr++) a[rr] += vds[rr][d] * w;
        }
        #pragma unroll
        for (int rr = 0; rr < 16; rr++) {
            int ii = d_idx32[r0 + rr];
            d_vraw[(size_t)(r0 + rr) * CCD + c] = tanhf(a[rr]) * vtab[(size_t)ii * CCD + c];
        }
    }
}

// =====================================================================
// K3: q/k time-shift + LayerNorm, warp-per-row
// =====================================================================
__global__ void qk_ln_kernel(int which, const float* __restrict__ coef,
                             const float* __restrict__ g, const float* __restrict__ bta) {
    const float* raw; int stride;
    __nv_bfloat16 *oh, *ol;
    if (which == 0) { raw = d_proj; stride = NPROJ; oh = d_qh; ol = d_ql; }
    else            { raw = d_kraw; stride = QD;    oh = d_kh; ol = d_kl; }
    const int r = blockIdx.x * 8 + (threadIdx.x >> 5);
    const int lane = threadIdx.x & 31;
    const int t = r & (TT - 1);
    const float* cur = raw + (size_t)r * stride;
    const float* prv = cur - stride;
    float y[8];
    float s = 0.f, s2 = 0.f;
    #pragma unroll
    for (int j = 0; j < 8; j++) {
        int d = j * 32 + lane;
        float c = cur[d];
        float p = (t > 0) ? prv[d] : 0.f;
        float v = c + (p - c) * coef[d];
        y[j] = v; s += v; s2 += v * v;
    }
    #pragma unroll
    for (int o = 16; o; o >>= 1) {
        s  += __shfl_xor_sync(0xffffffffu, s,  o);
        s2 += __shfl_xor_sync(0xffffffffu, s2, o);
    }
    float mean = s * (1.f / QD);
    float var  = s2 * (1.f / QD) - mean * mean;
    float rstd = rsqrtf(var + 1e-5f);
    #pragma unroll
    for (int j = 0; j < 8; j++) {
        int d = j * 32 + lane;
        float o = (y[j] - mean) * rstd * g[d] + bta[d];
        __nv_bfloat16 hi = __float2bfloat16(o);
        oh[(size_t)r * QD + d] = hi;
        ol[(size_t)r * QD + d] = __float2bfloat16(o - __bfloat162float(hi));
    }
}

// =====================================================================
// K3v: v shift+LN statistics only
// =====================================================================
__global__ void v_stats_kernel(const float* __restrict__ coef) {
    const int r = blockIdx.x * 8 + (threadIdx.x >> 5);
    const int lane = threadIdx.x & 31;
    const int t = r & (TT - 1);
    const float4* cur = (const float4*)(d_vraw + (size_t)r * CCD);
    const float4* prv = cur - CCD / 4;
    const float4* cf  = (const float4*)coef;
    float s = 0.f, s2 = 0.f;
    #pragma unroll
    for (int j = 0; j < 8; j++) {
        int d4 = j * 32 + lane;
        float4 c = cur[d4];
        float4 p = (t > 0) ? prv[d4] : make_float4(0.f, 0.f, 0.f, 0.f);
        float4 w = cf[d4];
        float vx = c.x + (p.x - c.x) * w.x;
        float vy = c.y + (p.y - c.y) * w.y;
        float vz = c.z + (p.z - c.z) * w.z;
        float vw = c.w + (p.w - c.w) * w.w;
        s  += vx + vy + vz + vw;
        s2 += vx * vx + vy * vy + vz * vz + vw * vw;
    }
    #pragma unroll
    for (int o = 16; o; o >>= 1) {
        s  += __shfl_xor_sync(0xffffffffu, s,  o);
        s2 += __shfl_xor_sync(0xffffffffu, s2, o);
    }
    if (lane == 0) {
        float mean = s * (1.f / CCD);
        float var  = s2 * (1.f / CCD) - mean * mean;
        d_vmean[r] = mean;
        d_vrstd[r] = rsqrtf(var + 1e-5f);
    }
}

// =====================================================================
// K3b: fused shift+LN+transpose+split: vraw -> Vt bf16 hi/lo
// =====================================================================
__global__ void vt_cvt_kernel(const float* __restrict__ xv, const float* __restrict__ gv,
                              const float* __restrict__ bv) {
    __shared__ float ts[33][33];
    const int c0 = blockIdx.x * 32;
    const int r0 = blockIdx.y * 32;
    for (int i2 = threadIdx.x; i2 < 33 * 32; i2 += 256) {
        int rr = i2 >> 5, cc = i2 & 31;
        int grow = r0 - 1 + rr;
        if (grow < 0) grow = 0;
        ts[rr][cc] = d_vraw[(size_t)grow * CCD + c0 + cc];
    }
    __syncthreads();
    const int lx = threadIdx.x & 31;
    const int ly = threadIdx.x >> 5;
    const int bz = r0 >> 11;
    const int t0 = r0 & (TT - 1);
    const int t  = t0 + lx;
    const int r  = r0 + lx;
    const float mean = d_vmean[r];
    const float rstd = d_vrstd[r];
    #pragma unroll
    for (int i = 0; i < 4; i++) {
        int cc = ly + i * 8;
        int c  = c0 + cc;
        float curv = ts[lx + 1][cc];
        float prev = (t > 0) ? ts[lx][cc] : 0.f;
        float y = curv + (prev - curv) * xv[c];
        float v = (y - mean) * rstd * gv[c] + bv[c];
        size_t o = (size_t)(bz * CCD + c) * TT + t;
        __nv_bfloat16 hi = __float2bfloat16(v);
        d_vth[o] = hi;
        d_vtl[o] = __float2bfloat16(v - __bfloat162float(hi));
    }
}

// =====================================================================
// K4a: score via mma.sync, cp.async 3-stage pipeline (k16)
// =====================================================================
__global__ void __launch_bounds__(256, 2) score_mma_kernel() {
    extern __shared__ char smem[];
    const int tj = blockIdx.x, ti = 15 - blockIdx.y, b = blockIdx.z;
    if (tj > ti) return;
    const uint32_t sb = smem_to_u32(smem);
    const int tid  = threadIdx.x;
    const int lane = tid & 31;
    const int wid  = tid >> 5;
    const int wm = wid & 1;
    const int wn = wid >> 1;
    const int g = lane >> 2, q = lane & 3;

    float acc[4][4][4] = {};

    const int lrow = tid >> 1;
    const int lh   = tid & 1;
    const size_t qoff = (size_t)(b * TT + ti * 128 + lrow) * QD + lh * 8;
    const size_t koff = (size_t)(b * TT + tj * 128 + lrow) * QD + lh * 8;
    const __nv_bfloat16* gsrc[4] = { d_qh + qoff, d_ql + qoff, d_kh + koff, d_kl + koff };
    const uint32_t sldst = sb + lrow * 48 + lh * 16;

    const int nc = QD / 16;             // 16 chunks

    #pragma unroll
    for (int p = 0; p < 2; p++) {
        #pragma unroll
        for (int a = 0; a < 4; a++) cp_async16(sldst + p * PV_STAGE + a * PV_ARR, gsrc[a] + p * 16);
        CP_COMMIT();
    }

    for (int c = 0; c < nc; c++) {
        const uint32_t st = (c % 3) * PV_STAGE;
        if (c + 2 < nc) {
            const uint32_t st2 = ((c + 2) % 3) * PV_STAGE;
            const int k1 = (c + 2) * 16;
            #pragma unroll
            for (int a = 0; a < 4; a++) cp_async16(sldst + st2 + a * PV_ARR, gsrc[a] + k1);
            CP_COMMIT();
            CP_WAIT2();
        } else {
            CP_WAIT0();
        }
        __syncthreads();
        {
            uint32_t bh[4][2], bl[4][2];
            const int brow = lane & 7;
            const uint32_t bsel = ((lane >> 3) & 1) * 16;
            #pragma unroll
            for (int ni = 0; ni < 4; ni++) {
                uint32_t boff = (wn * 32 + ni * 8 + brow) * 48 + bsel;
                ldsm2(bh[ni], sb + st + 2 * PV_ARR + boff);
                ldsm2(bl[ni], sb + st + 3 * PV_ARR + boff);
            }
            const int arow = wm * 64 + (lane & 15);
            const uint32_t asel = (lane >> 4) * 16;
            #pragma unroll
            for (int mi = 0; mi < 4; mi++) {
                uint32_t ah[4], al[4];
                uint32_t aoff = (arow + mi * 16) * 48 + asel;
                ldsm4(ah, sb + st + aoff);
                ldsm4(al, sb + st + 1 * PV_ARR + aoff);
                #pragma unroll
                for (int ni = 0; ni < 4; ni++) {
                    mma_bf16(acc[mi][ni], ah, bh[ni]);
                    mma_bf16(acc[mi][ni], ah, bl[ni]);
                    mma_bf16(acc[mi][ni], al, bh[ni]);
                }
            }
        }
        __syncthreads();
    }

    #pragma unroll
    for (int mi = 0; mi < 4; mi++) {
        const int tg0 = ti * 128 + wm * 64 + mi * 16 + g;
        const int tg1 = tg0 + 8;
        float ps0 = 0.f, ps1 = 0.f;
        #pragma unroll
        for (int ni = 0; ni < 4; ni++) {
            const int sg = tj * 128 + wn * 32 + ni * 8 + q * 2;
            #pragma unroll
            for (int e = 0; e < 4; e++) {
                const int col = sg + (e & 1);
                const int row = (e < 2) ? tg0 : tg1;
                float p = 0.f;
                if (col <= row) {
                    float d = acc[mi][ni][e];
                    float u = __expf(d * (1.f / 512.f));
                    float th = __fdividef(u - 1.f, u + 1.f);
                    p = __expf(64.f * th);
                }
                acc[mi][ni][e] = p;
                if (e < 2) ps0 += p; else ps1 += p;
            }
        }
        ps0 += __shfl_xor_sync(0xffffffffu, ps0, 1);
        ps0 += __shfl_xor_sync(0xffffffffu, ps0, 2);
        ps1 += __shfl_xor_sync(0xffffffffu, ps1, 1);
        ps1 += __shfl_xor_sync(0xffffffffu, ps1, 2);
        if (q == 0) {
            d_psum[(size_t)(b * TT + tg0) * 64 + tj * 4 + wn] = ps0;
            d_psum[(size_t)(b * TT + tg1) * 64 + tj * 4 + wn] = ps1;
        }
    }

    uint32_t* stg = (uint32_t*)smem;
    const int cpair = wn * 16 + q;
    for (int pass = 0; pass < 2; pass++) {
        __syncthreads();
        #pragma unroll
        for (int mi = 0; mi < 4; mi++) {
            const int r0 = wm * 64 + mi * 16 + g;
            #pragma unroll
            for (int ni = 0; ni < 4; ni++) {
                float v0 = acc[mi][ni][0], v1 = acc[mi][ni][1];
                float v2 = acc[mi][ni][2], v3 = acc[mi][ni][3];
                if (pass == 1) {
                    v0 -= __bfloat162float(__float2bfloat16(v0));
                    v1 -= __bfloat162float(__float2bfloat16(v1));
                    v2 -= __bfloat162float(__float2bfloat16(v2));
                    v3 -= __bfloat162float(__float2bfloat16(v3));
                }
                stg[r0 * 68 + cpair + ni * 4]       = pack_bf16x2(v0, v1);
                stg[(r0 + 8) * 68 + cpair + ni * 4] = pack_bf16x2(v2, v3);
            }
        }
        __syncthreads();
        __nv_bfloat16* gbase = (pass == 0) ? d_ph : d_pl;
        const int srow = tid >> 1;
        const int c0 = (tid & 1) * 32;
        uint4* gp = (uint4*)(gbase + (size_t)(b * TT + ti * 128 + srow) * TT
                             + (size_t)tj * 128 + (tid & 1) * 64);
        const uint4* sp = (const uint4*)(stg + srow * 68 + c0);
        #pragma unroll
        for (int i = 0; i < 8; i++) gp[i] = sp[i];
    }
}

// =====================================================================
// K4c: rowsum from 32-col stripe partials
// =====================================================================
__global__ void psum_reduce_kernel() {
    int r = blockIdx.x * 256 + threadIdx.x;
    int t = r & (TT - 1);
    int n = (t >> 5) + 1;
    const float* p = d_psum + (size_t)r * 64;
    float s = 0.f;
    for (int j = 0; j < n; j++) s += p[j];
    d_rowsum[r] = s;
}

// =====================================================================
// K4b: PV via mma.sync, cp.async 3-stage pipeline (k16)
// =====================================================================
__global__ void __launch_bounds__(256, 2) pv_mma_kernel(float* __restrict__ out) {
    extern __shared__ char smem[];
    const int cb = blockIdx.x, ti = 15 - blockIdx.y, b = blockIdx.z;
    const uint32_t sb = smem_to_u32(smem);
    const int tid  = threadIdx.x;
    const int lane = tid & 31;
    const int wid  = tid >> 5;
    const int wm = wid & 1;
    const int wn = wid >> 1;
    const int g = lane >> 2, q = lane & 3;

    float acc[4][4][4] = {};

    const int lrow = tid >> 1;
    const int lh   = tid & 1;
    const size_t poff = (size_t)(b * TT + ti * 128 + lrow) * TT + lh * 8;
    const size_t voff = (size_t)(b * CCD + cb * 128 + lrow) * TT + lh * 8;
    const __nv_bfloat16* gsrc[4] = { d_ph + poff, d_pl + poff, d_vth + voff, d_vtl + voff };
    const uint32_t sldst = sb + lrow * 48 + lh * 16;

    const int nc = (ti + 1) * 8;

    #pragma unroll
    for (int p = 0; p < 2; p++) {
        #pragma unroll
        for (int a = 0; a < 4; a++) cp_async16(sldst + p * PV_STAGE + a * PV_ARR, gsrc[a] + p * 16);
        CP_COMMIT();
    }

    for (int c = 0; c < nc; c++) {
        const uint32_t st = (c % 3) * PV_STAGE;
        if (c + 2 < nc) {
            const uint32_t st2 = ((c + 2) % 3) * PV_STAGE;
            const int k1 = (c + 2) * 16;
            #pragma unroll
            for (int a = 0; a < 4; a++) cp_async16(sldst + st2 + a * PV_ARR, gsrc[a] + k1);
            CP_COMMIT();
            CP_WAIT2();
        } else {
            CP_WAIT0();
        }
        __syncthreads();
        {
            uint32_t bh[4][2], bl[4][2];
            const int brow = lane & 7;
            const uint32_t bsel = ((lane >> 3) & 1) * 16;
            #pragma unroll
            for (int ni = 0; ni < 4; ni++) {
                uint32_t boff = (wn * 32 + ni * 8 + brow) * 48 + bsel;
                ldsm2(bh[ni], sb + st + 2 * PV_ARR + boff);
                ldsm2(bl[ni], sb + st + 3 * PV_ARR + boff);
            }
            const int arow = wm * 64 + (lane & 15);
            const uint32_t asel = (lane >> 4) * 16;
            #pragma unroll
            for (int mi = 0; mi < 4; mi++) {
                uint32_t ah[4], al[4];
                uint32_t aoff = (arow + mi * 16) * 48 + asel;
                ldsm4(ah, sb + st + aoff);
                ldsm4(al, sb + st + 1 * PV_ARR + aoff);
                #pragma unroll
                for (int ni = 0; ni < 4; ni++) {
                    mma_bf16(acc[mi][ni], ah, bh[ni]);
                    mma_bf16(acc[mi][ni], ah, bl[ni]);
                    mma_bf16(acc[mi][ni], al, bh[ni]);
                }
            }
        }
        __syncthreads();
    }

    float inv0[4], inv1[4];
    #pragma unroll
    for (int mi = 0; mi < 4; mi++) {
        int rg = b * TT + ti * 128 + wm * 64 + mi * 16 + g;
        inv0[mi] = 1.f / d_rowsum[rg];
        inv1[mi] = 1.f / d_rowsum[rg + 8];
    }

    float* stg = (float*)smem;
    for (int h = 0; h < 2; h++) {
        __syncthreads();
        if ((wn >> 1) == h) {
            const int cbase = (wn & 1) * 32 + q * 2;
            #pragma unroll
            for (int mi = 0; mi < 4; mi++) {
                const int r0 = wm * 64 + mi * 16 + g;
                #pragma unroll
                for (int ni = 0; ni < 4; ni++) {
                    const int c = cbase + ni * 8;
                    stg[r0 * 68 + c]           = acc[mi][ni][0] * inv0[mi];
                    stg[r0 * 68 + c + 1]       = acc[mi][ni][1] * inv0[mi];
                    stg[(r0 + 8) * 68 + c]     = acc[mi][ni][2] * inv1[mi];
                    stg[(r0 + 8) * 68 + c + 1] = acc[mi][ni][3] * inv1[mi];
                }
            }
        }
        __syncthreads();
        const int srow = tid >> 1;
        const int c0 = (tid & 1) * 32;
        float4* gp = (float4*)(out + (size_t)(b * TT + ti * 128 + srow) * CCD
                               + (size_t)cb * 128 + h * 64 + c0);
        const float4* sp = (const float4*)(stg + srow * 68 + c0);
        #pragma unroll
        for (int i = 0; i < 8; i++) gp[i] = sp[i];
    }
}

// =====================================================================
extern "C" void kernel_launch(void* const* d_in, const int* in_sizes, int n_in,
                              void* d_out, int out_size) {
    const float* x     = (const float*)d_in[0];
    const void*  idx   = d_in[1];
    const float* Wqq   = (const float*)d_in[2];
    const float* Wk    = (const float*)d_in[3];
    const float* Wkup  = (const float*)d_in[4];
    const float* Wv    = (const float*)d_in[5];
    const float* Wvup  = (const float*)d_in[6];
    const float* ktab  = (const float*)d_in[7];
    const float* vtab  = (const float*)d_in[8];
    const float* xq    = (const float*)d_in[9];
    const float* xk    = (const float*)d_in[10];
    const float* xv    = (const float*)d_in[11];
    const float* gq    = (const float*)d_in[12];
    const float* bq    = (const float*)d_in[13];
    const float* gk    = (const float*)d_in[14];
    const float* bk    = (const float*)d_in[15];
    const float* gv    = (const float*)d_in[16];
    const float* bv    = (const float*)d_in[17];
    float* out = (float*)d_out;

    // raise dyn-smem ceilings (host-side attribute set; not a graph node, no alloc)
    static bool attr_done = false;
    if (!attr_done) {
        cudaFuncSetAttribute(proj_mma_kernel,  cudaFuncAttributeMaxDynamicSharedMemorySize, PJ_SMEM);
        cudaFuncSetAttribute(score_mma_kernel, cudaFuncAttributeMaxDynamicSharedMemorySize, PV_SMEM);
        cudaFuncSetAttribute(pv_mma_kernel,    cudaFuncAttributeMaxDynamicSharedMemorySize, PV_SMEM);
        attr_done = true;
    }

    idx_cvt_kernel<<<NROWS / 256, 256>>>(idx);
    xsplit_kernel<<<NROWS * CCD / 4 / 256, 256>>>(x, NROWS * CCD / 4);
    wsplit_kernel<<<NPROJ * CCD / 4 / 256, 256>>>(Wqq, Wk, Wv);
    proj_mma_kernel<<<dim3(5, 64), 256, PJ_SMEM>>>();
    kup_kernel<<<NROWS / 32, 256>>>(Wkup, ktab);
    vup_kernel<<<NROWS / 16, 256>>>(Wvup, vtab);
    qk_ln_kernel<<<NROWS / 8, 256>>>(0, xq, gq, bq);
    qk_ln_kernel<<<NROWS / 8, 256>>>(1, xk, gk, bk);
    v_stats_kernel<<<NROWS / 8, 256>>>(xv);
    vt_cvt_kernel<<<dim3(CCD / 32, NROWS / 32), 256>>>(xv, gv, bv);
    score_mma_kernel<<<dim3(16, 16, 4), 256, PV_SMEM>>>();
    psum_reduce_kernel<<<NROWS / 256, 256>>>();
    pv_mma_kernel<<<dim3(8, 16, 4), 256, PV_SMEM>>>(out);
}